// round 12
// baseline (speedup 1.0000x reference)
#include <cuda_runtime.h>
#include <math.h>
#include <stdint.h>

// Problem constants (fixed shapes)
#define B_  16
#define C_  128
#define H_  64
#define W_  64
#define G_  4
#define CG_ 32
#define HW_ 4096      // H_*W_
#define HS_ 128
#define WS_ 128

// Scratch (static device globals; no runtime allocation)
__device__ uint32_t d_Wt[C_ * C_];         // Wt[k][n] = tf32(w_proj[n,k] * bn_scale[n])
__device__ float d_tb[C_];                 // folded bias
__device__ float d_p[B_ * G_ * HW_ * CG_]; // p in (b,g,pix,cg) layout, 33.5MB
__device__ float d_off[B_ * 8 * HW_];      // tanh offsets, NCHW (B,2G,H,W)

__device__ __forceinline__ uint32_t to_tf32(float v) {
    uint32_t u;
    asm("cvt.rna.tf32.f32 %0, %1;" : "=r"(u) : "f"(v));
    return u;
}

// ---------------------------------------------------------------------------
// K0: fold BN into transposed weights (tf32-rounded) + folded bias
// ---------------------------------------------------------------------------
__global__ void k0_prep(const float* __restrict__ w_proj,
                        const float* __restrict__ gamma,
                        const float* __restrict__ beta,
                        const float* __restrict__ mean,
                        const float* __restrict__ var) {
    int idx = blockIdx.x * blockDim.x + threadIdx.x;
    if (idx >= C_ * C_) return;
    int k = idx >> 7;        // in-channel (GEMM K)
    int n = idx & 127;       // out-channel (GEMM N)
    float s = gamma[n] * rsqrtf(var[n] + 1e-5f);
    d_Wt[k * C_ + n] = to_tf32(w_proj[n * C_ + k] * s);
    if (idx < C_) {
        d_tb[idx] = beta[idx] - mean[idx] * (gamma[idx] * rsqrtf(var[idx] + 1e-5f));
    }
}

// ---------------------------------------------------------------------------
// K1: 1x1 conv as TF32 mma.sync GEMM, double-buffered 16-k panels.
//     8 warps, warp tile 32x64 (2x8 m16n8k8). grid (HW/128, B).
// ---------------------------------------------------------------------------
#define KP    16
#define SKSTR 136
__global__ __launch_bounds__(256) void k1_mma(const float* __restrict__ x) {
    __shared__ uint32_t As[2][KP * SKSTR];
    __shared__ uint32_t Bs[2][KP * SKSTR];
    __shared__ float sTb[128];

    int b = blockIdx.y;
    int pix0 = blockIdx.x * 128;
    int t = threadIdx.x;
    int wid = t >> 5;
    int lane = t & 31;
    int gid = lane >> 2;
    int tg = lane & 3;
    int mbase = (wid & 3) * 32;
    int nbase = (wid >> 2) * 64;

    if (t < 128) sTb[t] = d_tb[t];

    const float* xb = x + (size_t)b * C_ * HW_ + pix0;

    int fk[2], fc[2];
#pragma unroll
    for (int i = 0; i < 2; i++) {
        int s = t + i * 256;
        fk[i] = s >> 5;
        fc[i] = (s & 31) * 4;
    }

    float4 stg[2];

#define K1_STAGE_A(p) do { _Pragma("unroll") \
    for (int i = 0; i < 2; i++) \
        stg[i] = *(const float4*)&xb[(size_t)((p) * KP + fk[i]) * HW_ + fc[i]]; } while (0)

#define K1_COMMIT_A(p) do { uint32_t* Ad = As[(p) & 1]; _Pragma("unroll") \
    for (int i = 0; i < 2; i++) { uint32_t* d = Ad + fk[i] * SKSTR + fc[i]; \
        d[0] = to_tf32(stg[i].x); d[1] = to_tf32(stg[i].y); \
        d[2] = to_tf32(stg[i].z); d[3] = to_tf32(stg[i].w); } } while (0)

#define K1_FILL_B(p) do { \
    uint32_t sb = (uint32_t)__cvta_generic_to_shared(Bs[(p) & 1]); \
    _Pragma("unroll") for (int i = 0; i < 2; i++) { \
        uint32_t dst = sb + (uint32_t)(fk[i] * SKSTR + fc[i]) * 4u; \
        const uint32_t* src = d_Wt + ((p) * KP + fk[i]) * C_ + fc[i]; \
        asm volatile("cp.async.ca.shared.global [%0], [%1], 16;" :: "r"(dst), "l"(src)); } \
    asm volatile("cp.async.commit_group;"); } while (0)

    K1_STAGE_A(0);
    K1_FILL_B(0);
    K1_COMMIT_A(0);
    asm volatile("cp.async.wait_group 0;" ::: "memory");
    __syncthreads();

    float acc[2][8][4];
#pragma unroll
    for (int mt = 0; mt < 2; mt++)
#pragma unroll
        for (int nt = 0; nt < 8; nt++)
#pragma unroll
            for (int z = 0; z < 4; z++) acc[mt][nt][z] = 0.f;

#pragma unroll 1
    for (int p = 0; p < 8; p++) {
        if (p < 7) { K1_STAGE_A(p + 1); K1_FILL_B(p + 1); }

        const uint32_t* A = As[p & 1];
        const uint32_t* Bp = Bs[p & 1];

#pragma unroll
        for (int ks = 0; ks < 2; ks++) {
            int kk = ks * 8;
            uint32_t a[2][4];
#pragma unroll
            for (int mt = 0; mt < 2; mt++) {
                int m = mbase + mt * 16 + gid;
                const uint32_t* ap = A + (kk + tg) * SKSTR + m;
                a[mt][0] = ap[0];
                a[mt][1] = ap[8];
                a[mt][2] = ap[4 * SKSTR];
                a[mt][3] = ap[4 * SKSTR + 8];
            }
#pragma unroll
            for (int nt = 0; nt < 8; nt++) {
                int n = nbase + nt * 8 + gid;
                uint32_t b0 = Bp[(kk + tg) * SKSTR + n];
                uint32_t b1 = Bp[(kk + tg + 4) * SKSTR + n];
#pragma unroll
                for (int mt = 0; mt < 2; mt++) {
                    asm volatile(
                        "mma.sync.aligned.m16n8k8.row.col.f32.tf32.tf32.f32 "
                        "{%0,%1,%2,%3}, {%4,%5,%6,%7}, {%8,%9}, {%0,%1,%2,%3};"
                        : "+f"(acc[mt][nt][0]), "+f"(acc[mt][nt][1]),
                          "+f"(acc[mt][nt][2]), "+f"(acc[mt][nt][3])
                        : "r"(a[mt][0]), "r"(a[mt][1]), "r"(a[mt][2]), "r"(a[mt][3]),
                          "r"(b0), "r"(b1));
                }
            }
        }

        if (p < 7) {
            K1_COMMIT_A(p + 1);
            asm volatile("cp.async.wait_group 0;" ::: "memory");
        }
        __syncthreads();
    }

#pragma unroll
    for (int mt = 0; mt < 2; mt++) {
        int pixA = pix0 + mbase + mt * 16 + gid;
        int pixB = pixA + 8;
#pragma unroll
        for (int nt = 0; nt < 8; nt++) {
            int n = nbase + nt * 8 + 2 * tg;
            int g = n >> 5, cg = n & 31;
            float t0 = sTb[n], t1 = sTb[n + 1];
            float u;
            float2 vA, vB;
            u = acc[mt][nt][0] + t0; vA.x = u * (1.f / (1.f + __expf(-u)));
            u = acc[mt][nt][1] + t1; vA.y = u * (1.f / (1.f + __expf(-u)));
            u = acc[mt][nt][2] + t0; vB.x = u * (1.f / (1.f + __expf(-u)));
            u = acc[mt][nt][3] + t1; vB.y = u * (1.f / (1.f + __expf(-u)));
            float* base = d_p + ((size_t)(b * G_ + g) * HW_) * CG_ + cg;
            *(float2*)(base + (size_t)pixA * CG_) = vA;
            *(float2*)(base + (size_t)pixB * CG_) = vB;
        }
    }
}

// ---------------------------------------------------------------------------
// K2T: 3x3 offset conv (128ch -> 8oc) as TF32 mma over 9 taps.
//      Extracted verbatim from the validated R9 fused kernel (K2 half only).
//      A panels: [k][4 rows][68] pitch 280, data at col 4..67, guards zeroed
//      => tap shifts read true zero padding. 4 panels of 32k, double-buffered.
//      Block = 2 image rows (128 px). grid (32, B). 256 thr, 8 warps.
//      Writes d_off directly (bias + tanh). No k-split, no reduce pass.
// ---------------------------------------------------------------------------
#define APITCH 280
#define AROW   68
#define ABUF   (32 * APITCH)                       // 8960 words
#define SMEMK2 ((2 * ABUF + 9 * 128 * 8) * 4)      // 108544 bytes

__global__ __launch_bounds__(256) void k2t(const float* __restrict__ x,
                                           const float* __restrict__ w_off,
                                           const float* __restrict__ b_off) {
    extern __shared__ uint32_t dsm[];
    uint32_t* Ab[2] = { dsm, dsm + ABUF };
    uint32_t* Wso   = dsm + 2 * ABUF;              // [tap][k][oc] stride 8

    int b = blockIdx.y;
    int pix0 = blockIdx.x * 128;
    int h0 = blockIdx.x * 2;
    int t = threadIdx.x;
    int wid = t >> 5;
    int lane = t & 31;
    int gid = lane >> 2;
    int tg = lane & 3;

    // one-time init: zero guards, load tap weights (tf32)
    for (int i = t; i < 2 * ABUF; i += 256) dsm[i] = 0u;
    for (int i = t; i < 9 * 128 * 8; i += 256) {
        int tap = i >> 10;
        int rem = i & 1023;
        int c = rem >> 3;
        int oc = rem & 7;
        Wso[(tap * 128 + c) * 8 + oc] = to_tf32(w_off[oc * 1152 + c * 9 + tap]);
    }

    const float* xb = x + (size_t)b * C_ * HW_;

    // A-fill slots: r = halo row 0..3 (h0-1..h0+2), q = quad, kb = ch base
    int r = (t >> 4) & 3;
    int q = t & 15;
    int kb = t >> 6;                 // 0..3; channels kb+4i, i<8
    int hh = h0 - 1 + r;
    bool hv = (hh >= 0 && hh < H_);
    const float* asrc = xb + hh * W_ + q * 4;
    int adst = kb * APITCH + r * AROW + 4 + q * 4;

    float4 st[8];

#define K2_STAGE(p) do { if (hv) { _Pragma("unroll") \
    for (int i = 0; i < 8; i++) \
        st[i] = *(const float4*)(asrc + (size_t)((p) * 32 + kb + i * 4) * HW_); } } while (0)

#define K2_COMMIT(p) do { if (hv) { uint32_t* Ad = Ab[(p) & 1]; _Pragma("unroll") \
    for (int i = 0; i < 8; i++) { uint32_t* d = Ad + adst + i * 4 * APITCH; \
        d[0] = to_tf32(st[i].x); d[1] = to_tf32(st[i].y); \
        d[2] = to_tf32(st[i].z); d[3] = to_tf32(st[i].w); } } } while (0)

    __syncthreads();                 // zeros + Wso visible
    K2_STAGE(0);
    K2_COMMIT(0);
    __syncthreads();

    float acc2[4] = {0.f, 0.f, 0.f, 0.f};
    int row2 = 1 + (wid >> 2);
    int col2 = 4 + (wid & 3) * 16 + gid;

#pragma unroll 1
    for (int p = 0; p < 4; p++) {
        if (p < 3) K2_STAGE(p + 1);

        const uint32_t* A = Ab[p & 1];

#pragma unroll
        for (int tap = 0; tap < 9; tap++) {
            int dy = tap / 3 - 1;
            int dx = tap - (tap / 3) * 3 - 1;
            int aoff = (row2 + dy) * AROW + col2 + dx;
#pragma unroll
            for (int kc = 0; kc < 4; kc++) {
                int kk = kc * 8;
                const uint32_t* ap = A + (kk + tg) * APITCH + aoff;
                uint32_t a0 = ap[0];
                uint32_t a1 = ap[8];
                uint32_t a2 = ap[4 * APITCH];
                uint32_t a3 = ap[4 * APITCH + 8];
                int wb = (tap * 128 + p * 32 + kk + tg) * 8 + gid;
                uint32_t b0 = Wso[wb];
                uint32_t b1 = Wso[wb + 32];
                asm volatile(
                    "mma.sync.aligned.m16n8k8.row.col.f32.tf32.tf32.f32 "
                    "{%0,%1,%2,%3}, {%4,%5,%6,%7}, {%8,%9}, {%0,%1,%2,%3};"
                    : "+f"(acc2[0]), "+f"(acc2[1]), "+f"(acc2[2]), "+f"(acc2[3])
                    : "r"(a0), "r"(a1), "r"(a2), "r"(a3), "r"(b0), "r"(b1));
            }
        }

        if (p < 3) K2_COMMIT(p + 1);
        __syncthreads();
    }

    // epilogue: bias + tanh -> d_off (NCHW)
    {
        int px = wid * 16 + gid;
        int oc0 = 2 * tg;
        float bo0 = b_off[oc0];
        float bo1 = b_off[oc0 + 1];
        float* o0 = d_off + (size_t)(b * 8 + oc0) * HW_ + pix0 + px;
        float* o1 = d_off + (size_t)(b * 8 + oc0 + 1) * HW_ + pix0 + px;
        o0[0] = tanhf(acc2[0] + bo0);
        o1[0] = tanhf(acc2[1] + bo1);
        o0[8] = tanhf(acc2[2] + bo0);
        o1[8] = tanhf(acc2[3] + bo1);
    }
}

// ---------------------------------------------------------------------------
// K3: offset upsample + grid_sample, channel-major smem tile, warp=channel,
//     direct coalesced stores. Block = 8x32 output px, 512 thr.
// ---------------------------------------------------------------------------
#define CSTR 127
#define K3TW 18
#define K3TH 7
__global__ __launch_bounds__(512) void k3_sample(float* __restrict__ out) {
    int bx = blockIdx.x;
    int ys0 = (bx >> 2) * 8;
    int xs0 = (bx & 3) * 32;
    int g = blockIdx.y;
    int b = blockIdx.z;
    int tid = threadIdx.x;
    int warp = tid >> 5;
    int lane = tid & 31;

    __shared__ float tile[CG_ * CSTR];
    __shared__ int   s_r[8][32][4];
    __shared__ float s_f[8][32][2];

    const float SY = 63.0f / 127.0f;
    const float SO = 63.0f / 128.0f;

    int x_lo = max(0, (int)floorf(xs0 * SY - 0.4923f));
    int y_lo = max(0, (int)floorf(ys0 * SY - 0.4923f));

    const float* pb = d_p + (size_t)(b * G_ + g) * HW_ * CG_;
    {
        uint32_t st0 = (uint32_t)__cvta_generic_to_shared(&tile[0]);
#pragma unroll
        for (int idx = tid; idx < K3TH * K3TW * CG_; idx += 512) {
            int p = idx >> 5;
            int c = idx & 31;
            int y = min(y_lo + p / K3TW, H_ - 1);
            int xx = min(x_lo + p % K3TW, W_ - 1);
            const float* src = &pb[(y * W_ + xx) * CG_ + c];
            asm volatile("cp.async.ca.shared.global [%0], [%1], 4;"
                         :: "r"(st0 + (uint32_t)(c * CSTR + p) * 4u), "l"(src));
        }
        asm volatile("cp.async.commit_group;");
    }

    if (tid < 256) {
        int r = tid >> 5;
        int xl = tid & 31;
        int ys = ys0 + r;
        int xs = xs0 + xl;

        float py = ys * SY;
        int y0u = (int)py;
        float wyu = py - y0u;
        int y1u = min(y0u + 1, H_ - 1);
        float px = xs * SY;
        int x0u = (int)px;
        float wxu = px - x0u;
        int x1u = min(x0u + 1, W_ - 1);

        const float* offx = d_off + (size_t)(b * 8 + 2 * g) * HW_;
        const float* offy = offx + HW_;

        float a00 = offx[y0u * W_ + x0u], a01 = offx[y0u * W_ + x1u];
        float a10 = offx[y1u * W_ + x0u], a11 = offx[y1u * W_ + x1u];
        float o_x = (a00 * (1.f - wxu) + a01 * wxu) * (1.f - wyu)
                  + (a10 * (1.f - wxu) + a11 * wxu) * wyu;

        float c00 = offy[y0u * W_ + x0u], c01 = offy[y0u * W_ + x1u];
        float c10 = offy[y1u * W_ + x0u], c11 = offy[y1u * W_ + x1u];
        float o_y = (c00 * (1.f - wxu) + c01 * wxu) * (1.f - wyu)
                  + (c10 * (1.f - wxu) + c11 * wxu) * wyu;

        float ix = fminf(fmaxf(px + o_x * SO, 0.f), (float)(W_ - 1));
        float iy = fminf(fmaxf(py + o_y * SO, 0.f), (float)(H_ - 1));

        int ix0 = (int)ix; if (ix0 > W_ - 1) ix0 = W_ - 1;
        int iy0 = (int)iy; if (iy0 > H_ - 1) iy0 = H_ - 1;
        int ix1 = min(ix0 + 1, W_ - 1);
        int iy1 = min(iy0 + 1, H_ - 1);

        int base = (iy0 - y_lo) * K3TW + (ix0 - x_lo);
        int dxo = ix1 - ix0;
        int dyo = (iy1 - iy0) * K3TW;
        s_r[r][xl][0] = base;
        s_r[r][xl][1] = base + dxo;
        s_r[r][xl][2] = base + dyo;
        s_r[r][xl][3] = base + dyo + dxo;
        s_f[r][xl][0] = ix - ix0;
        s_f[r][xl][1] = iy - iy0;
    }

    asm volatile("cp.async.wait_group 0;" ::: "memory");
    __syncthreads();

#pragma unroll
    for (int h = 0; h < 2; h++) {
        int c = warp + h * 16;
        const float* tc = &tile[c * CSTR];
        float* ob = out + ((size_t)(b * C_ + g * CG_ + c) * HS_ + ys0) * WS_ + xs0 + lane;
#pragma unroll
        for (int r = 0; r < 8; r++) {
            int4 rr = *(const int4*)&s_r[r][lane][0];
            float fx = s_f[r][lane][0];
            float fy = s_f[r][lane][1];
            float v00 = tc[rr.x], v01 = tc[rr.y], v10 = tc[rr.z], v11 = tc[rr.w];
            float t0 = v00 * (1.f - fx) + v01 * fx;
            float t1 = v10 * (1.f - fx) + v11 * fx;
            ob[(size_t)r * WS_] = t0 * (1.f - fy) + t1 * fy;
        }
    }
}

// ---------------------------------------------------------------------------
// Launcher: fork-join two-stream schedule (graph-capturable).
//   null stream:  k2t ---------\
//   side stream:  k0 -> k1 -----+--> k3
// ---------------------------------------------------------------------------
extern "C" void kernel_launch(void* const* d_in, const int* in_sizes, int n_in,
                              void* d_out, int out_size) {
    const float* x      = (const float*)d_in[0];
    const float* w_off  = (const float*)d_in[1];
    const float* b_off  = (const float*)d_in[2];
    const float* w_proj = (const float*)d_in[3];
    const float* gamma  = (const float*)d_in[4];
    const float* beta   = (const float*)d_in[5];
    const float* mean   = (const float*)d_in[6];
    const float* var    = (const float*)d_in[7];
    float* out = (float*)d_out;

    static cudaStream_t s2 = nullptr;
    static cudaEvent_t evFork = nullptr, evJoin = nullptr;
    if (s2 == nullptr) {
        cudaStreamCreateWithFlags(&s2, cudaStreamNonBlocking);
        cudaEventCreateWithFlags(&evFork, cudaEventDisableTiming);
        cudaEventCreateWithFlags(&evJoin, cudaEventDisableTiming);
        cudaFuncSetAttribute(k2t, cudaFuncAttributeMaxDynamicSharedMemorySize, SMEMK2);
    }

    // fork: side stream inherits the capture dependency
    cudaEventRecord(evFork, 0);
    cudaStreamWaitEvent(s2, evFork, 0);

    // side stream: weight prep -> projection GEMM
    k0_prep<<<64, 256, 0, s2>>>(w_proj, gamma, beta, mean, var);
    dim3 g1(HW_ / 128, B_);
    k1_mma<<<g1, 256, 0, s2>>>(x);
    cudaEventRecord(evJoin, s2);

    // null stream: tensor-core 3x3 offset conv (writes d_off directly)
    k2t<<<dim3(32, B_), 256, SMEMK2>>>(x, w_off, b_off);

    // join, then sample
    cudaStreamWaitEvent(0, evJoin, 0);
    dim3 g3((HS_ / 8) * (WS_ / 32), G_, B_);
    k3_sample<<<g3, 512>>>(out);
}

// round 13
// speedup vs baseline: 1.1095x; 1.1095x over previous
#include <cuda_runtime.h>
#include <math.h>
#include <stdint.h>

// Problem constants (fixed shapes)
#define B_  16
#define C_  128
#define H_  64
#define W_  64
#define G_  4
#define CG_ 32
#define HW_ 4096      // H_*W_
#define HS_ 128
#define WS_ 128

// Scratch (static device globals; no runtime allocation)
__device__ uint32_t d_Wt[C_ * C_];         // Wt[k][n] = tf32(w_proj[n,k] * bn_scale[n])
__device__ float d_tb[C_];                 // folded bias
__device__ float d_p[B_ * G_ * HW_ * CG_]; // p in (b,g,pix,cg) layout, 33.5MB
__device__ float d_off[B_ * 8 * HW_];      // tanh offsets, NCHW (B,2G,H,W)
__device__ float d_part[4 * B_ * 8 * HW_]; // K2 k-split partial sums, 8MB

// ---- packed fp32x2 helpers ----
__device__ __forceinline__ float2 fma2(float2 a, float2 b, float2 c) {
    float2 d;
    asm("fma.rn.f32x2 %0, %1, %2, %3;"
        : "=l"(reinterpret_cast<unsigned long long&>(d))
        : "l"(reinterpret_cast<unsigned long long&>(a)),
          "l"(reinterpret_cast<unsigned long long&>(b)),
          "l"(reinterpret_cast<unsigned long long&>(c)));
    return d;
}
__device__ __forceinline__ float2 mul2(float2 a, float2 b) {
    float2 d;
    asm("mul.rn.f32x2 %0, %1, %2;"
        : "=l"(reinterpret_cast<unsigned long long&>(d))
        : "l"(reinterpret_cast<unsigned long long&>(a)),
          "l"(reinterpret_cast<unsigned long long&>(b)));
    return d;
}
__device__ __forceinline__ uint32_t to_tf32(float v) {
    uint32_t u;
    asm("cvt.rna.tf32.f32 %0, %1;" : "=r"(u) : "f"(v));
    return u;
}

// ---------------------------------------------------------------------------
// K0: fold BN into transposed weights (tf32-rounded) + folded bias
// ---------------------------------------------------------------------------
__global__ void k0_prep(const float* __restrict__ w_proj,
                        const float* __restrict__ gamma,
                        const float* __restrict__ beta,
                        const float* __restrict__ mean,
                        const float* __restrict__ var) {
    int idx = blockIdx.x * blockDim.x + threadIdx.x;
    if (idx >= C_ * C_) return;
    int k = idx >> 7;
    int n = idx & 127;
    float s = gamma[n] * rsqrtf(var[n] + 1e-5f);
    d_Wt[k * C_ + n] = to_tf32(w_proj[n * C_ + k] * s);
    if (idx < C_) {
        d_tb[idx] = beta[idx] - mean[idx] * (gamma[idx] * rsqrtf(var[idx] + 1e-5f));
    }
}

// ---------------------------------------------------------------------------
// K1: 1x1 conv as TF32 mma.sync GEMM, double-buffered 16-k panels.
// ---------------------------------------------------------------------------
#define KP    16
#define SKSTR 136
__global__ __launch_bounds__(256) void k1_mma(const float* __restrict__ x) {
    __shared__ uint32_t As[2][KP * SKSTR];
    __shared__ uint32_t Bs[2][KP * SKSTR];
    __shared__ float sTb[128];

    int b = blockIdx.y;
    int pix0 = blockIdx.x * 128;
    int t = threadIdx.x;
    int wid = t >> 5;
    int lane = t & 31;
    int gid = lane >> 2;
    int tg = lane & 3;
    int mbase = (wid & 3) * 32;
    int nbase = (wid >> 2) * 64;

    if (t < 128) sTb[t] = d_tb[t];

    const float* xb = x + (size_t)b * C_ * HW_ + pix0;

    int fk[2], fc[2];
#pragma unroll
    for (int i = 0; i < 2; i++) {
        int s = t + i * 256;
        fk[i] = s >> 5;
        fc[i] = (s & 31) * 4;
    }

    float4 stg[2];

#define K1_STAGE_A(p) do { _Pragma("unroll") \
    for (int i = 0; i < 2; i++) \
        stg[i] = *(const float4*)&xb[(size_t)((p) * KP + fk[i]) * HW_ + fc[i]]; } while (0)

#define K1_COMMIT_A(p) do { uint32_t* Ad = As[(p) & 1]; _Pragma("unroll") \
    for (int i = 0; i < 2; i++) { uint32_t* d = Ad + fk[i] * SKSTR + fc[i]; \
        d[0] = to_tf32(stg[i].x); d[1] = to_tf32(stg[i].y); \
        d[2] = to_tf32(stg[i].z); d[3] = to_tf32(stg[i].w); } } while (0)

#define K1_FILL_B(p) do { \
    uint32_t sb = (uint32_t)__cvta_generic_to_shared(Bs[(p) & 1]); \
    _Pragma("unroll") for (int i = 0; i < 2; i++) { \
        uint32_t dst = sb + (uint32_t)(fk[i] * SKSTR + fc[i]) * 4u; \
        const uint32_t* src = d_Wt + ((p) * KP + fk[i]) * C_ + fc[i]; \
        asm volatile("cp.async.ca.shared.global [%0], [%1], 16;" :: "r"(dst), "l"(src)); } \
    asm volatile("cp.async.commit_group;"); } while (0)

    K1_STAGE_A(0);
    K1_FILL_B(0);
    K1_COMMIT_A(0);
    asm volatile("cp.async.wait_group 0;" ::: "memory");
    __syncthreads();

    float acc[2][8][4];
#pragma unroll
    for (int mt = 0; mt < 2; mt++)
#pragma unroll
        for (int nt = 0; nt < 8; nt++)
#pragma unroll
            for (int z = 0; z < 4; z++) acc[mt][nt][z] = 0.f;

#pragma unroll 1
    for (int p = 0; p < 8; p++) {
        if (p < 7) { K1_STAGE_A(p + 1); K1_FILL_B(p + 1); }

        const uint32_t* A = As[p & 1];
        const uint32_t* Bp = Bs[p & 1];

#pragma unroll
        for (int ks = 0; ks < 2; ks++) {
            int kk = ks * 8;
            uint32_t a[2][4];
#pragma unroll
            for (int mt = 0; mt < 2; mt++) {
                int m = mbase + mt * 16 + gid;
                const uint32_t* ap = A + (kk + tg) * SKSTR + m;
                a[mt][0] = ap[0];
                a[mt][1] = ap[8];
                a[mt][2] = ap[4 * SKSTR];
                a[mt][3] = ap[4 * SKSTR + 8];
            }
#pragma unroll
            for (int nt = 0; nt < 8; nt++) {
                int n = nbase + nt * 8 + gid;
                uint32_t b0 = Bp[(kk + tg) * SKSTR + n];
                uint32_t b1 = Bp[(kk + tg + 4) * SKSTR + n];
#pragma unroll
                for (int mt = 0; mt < 2; mt++) {
                    asm volatile(
                        "mma.sync.aligned.m16n8k8.row.col.f32.tf32.tf32.f32 "
                        "{%0,%1,%2,%3}, {%4,%5,%6,%7}, {%8,%9}, {%0,%1,%2,%3};"
                        : "+f"(acc[mt][nt][0]), "+f"(acc[mt][nt][1]),
                          "+f"(acc[mt][nt][2]), "+f"(acc[mt][nt][3])
                        : "r"(a[mt][0]), "r"(a[mt][1]), "r"(a[mt][2]), "r"(a[mt][3]),
                          "r"(b0), "r"(b1));
                }
            }
        }

        if (p < 7) {
            K1_COMMIT_A(p + 1);
            asm volatile("cp.async.wait_group 0;" ::: "memory");
        }
        __syncthreads();
    }

#pragma unroll
    for (int mt = 0; mt < 2; mt++) {
        int pixA = pix0 + mbase + mt * 16 + gid;
        int pixB = pixA + 8;
#pragma unroll
        for (int nt = 0; nt < 8; nt++) {
            int n = nbase + nt * 8 + 2 * tg;
            int g = n >> 5, cg = n & 31;
            float t0 = sTb[n], t1 = sTb[n + 1];
            float u;
            float2 vA, vB;
            u = acc[mt][nt][0] + t0; vA.x = u * (1.f / (1.f + __expf(-u)));
            u = acc[mt][nt][1] + t1; vA.y = u * (1.f / (1.f + __expf(-u)));
            u = acc[mt][nt][2] + t0; vB.x = u * (1.f / (1.f + __expf(-u)));
            u = acc[mt][nt][3] + t1; vB.y = u * (1.f / (1.f + __expf(-u)));
            float* base = d_p + ((size_t)(b * G_ + g) * HW_) * CG_ + cg;
            *(float2*)(base + (size_t)pixA * CG_) = vA;
            *(float2*)(base + (size_t)pixB * CG_) = vB;
        }
    }
}

// ---------------------------------------------------------------------------
// K2a: 3x3 conv partials, 32-channel k-slice, cp.async 4-deep pipeline.
// ---------------------------------------------------------------------------
#define XSTR 35
__global__ __launch_bounds__(256, 4) void k2a_conv3(const float* __restrict__ x,
                                                    const float* __restrict__ w_off) {
    __shared__ float ws[32 * 72];
    __shared__ float xbuf[4][18 * XSTR];

    int bz = blockIdx.z;
    int b = bz >> 2;
    int split = bz & 3;
    int k_lo = split * 32;
    int h0 = blockIdx.y * 16;
    int w0 = blockIdx.x * 32;
    int tid = threadIdx.y * 16 + threadIdx.x;
    int tx = threadIdx.x;
    int ty = threadIdx.y;

    for (int idx = tid; idx < 32 * 9 * 8; idx += 256) {
        int kk = idx / 72;
        int r = idx - kk * 72;
        int t = r >> 3;
        int oc = r & 7;
        ws[idx] = w_off[oc * (C_ * 9) + (k_lo + kk) * 9 + t];
    }
    for (int i = tid; i < 4 * 18 * XSTR; i += 256) ((float*)xbuf)[i] = 0.f;

    const float* xb = x + (size_t)b * C_ * HW_ + (size_t)k_lo * HW_;

    uint32_t soff[3];
    int goff[3];
    bool sval[3];
    uint32_t sb0 = (uint32_t)__cvta_generic_to_shared(&xbuf[0][0]);
#pragma unroll
    for (int i = 0; i < 3; i++) {
        int idx = tid + i * 256;
        int r = idx / 34, cc = idx - r * 34;
        int h = h0 - 1 + r, w = w0 - 1 + cc;
        soff[i] = (uint32_t)(r * XSTR + cc) * 4u;
        goff[i] = h * W_ + w;
        sval[i] = (idx < 612) && (h >= 0) && (h < H_) && (w >= 0) && (w < W_);
    }

    __syncthreads();

#pragma unroll
    for (int kk = 0; kk < 3; kk++) {
        const float* src = xb + (size_t)kk * HW_;
        uint32_t base = sb0 + (uint32_t)kk * (18 * XSTR * 4);
#pragma unroll
        for (int i = 0; i < 3; i++)
            if (sval[i])
                asm volatile("cp.async.ca.shared.global [%0], [%1], 4;"
                             :: "r"(base + soff[i]), "l"(src + goff[i]));
        asm volatile("cp.async.commit_group;");
    }

    float2 acc0[4], acc1[4];
#pragma unroll
    for (int q = 0; q < 4; q++) { acc0[q] = make_float2(0.f, 0.f); acc1[q] = make_float2(0.f, 0.f); }

    for (int k = 0; k < 32; k++) {
        asm volatile("cp.async.wait_group 2;" ::: "memory");
        __syncthreads();

        if (k + 3 < 32) {
            const float* src = xb + (size_t)(k + 3) * HW_;
            uint32_t base = sb0 + (uint32_t)((k + 3) & 3) * (18 * XSTR * 4);
#pragma unroll
            for (int i = 0; i < 3; i++)
                if (sval[i])
                    asm volatile("cp.async.ca.shared.global [%0], [%1], 4;"
                                 :: "r"(base + soff[i]), "l"(src + goff[i]));
        }
        asm volatile("cp.async.commit_group;");

        const float* xtc = &xbuf[k & 3][0];
        float xv[3][4];
#pragma unroll
        for (int r = 0; r < 3; r++)
#pragma unroll
            for (int c = 0; c < 4; c++) xv[r][c] = xtc[(ty + r) * XSTR + 2 * tx + c];

        const float* wk = &ws[k * 72];
#pragma unroll
        for (int t = 0; t < 9; t++) {
            int dy = t / 3, dx = t - dy * 3;
            float2 wp[4];
            *(float4*)&wp[0] = *(const float4*)&wk[t * 8 + 0];
            *(float4*)&wp[2] = *(const float4*)&wk[t * 8 + 4];
            float2 xp0 = make_float2(xv[dy][dx], xv[dy][dx]);
            float2 xp1 = make_float2(xv[dy][dx + 1], xv[dy][dx + 1]);
#pragma unroll
            for (int q = 0; q < 4; q++) {
                acc0[q] = fma2(xp0, wp[q], acc0[q]);
                acc1[q] = fma2(xp1, wp[q], acc1[q]);
            }
        }
    }

    int y = h0 + ty;
    int xw = w0 + 2 * tx;
    float* pbase = d_part + (size_t)(split * B_ + b) * 8 * HW_;
#pragma unroll
    for (int q = 0; q < 4; q++) {
        float a0[2] = { acc0[q].x, acc0[q].y };
        float a1[2] = { acc1[q].x, acc1[q].y };
#pragma unroll
        for (int h = 0; h < 2; h++) {
            int oc = q * 2 + h;
            size_t base = (size_t)oc * HW_ + y * W_ + xw;
            pbase[base] = a0[h];
            pbase[base + 1] = a1[h];
        }
    }
}

// ---------------------------------------------------------------------------
// K2b: reduce 4 partials + bias + tanh -> d_off
// ---------------------------------------------------------------------------
__global__ void k2b_reduce(const float* __restrict__ b_off) {
    int i = blockIdx.x * blockDim.x + threadIdx.x;
    const int N4 = B_ * 8 * HW_ / 4;
    if (i >= N4) return;
    int e = i * 4;
    int r = e & (8 * HW_ - 1);
    int b = e / (8 * HW_);
    int oc = r / HW_;

    const float4* p0 = (const float4*)(d_part + ((size_t)(0 * B_ + b) * 8) * HW_ + r);
    const float4* p1 = (const float4*)(d_part + ((size_t)(1 * B_ + b) * 8) * HW_ + r);
    const float4* p2 = (const float4*)(d_part + ((size_t)(2 * B_ + b) * 8) * HW_ + r);
    const float4* p3 = (const float4*)(d_part + ((size_t)(3 * B_ + b) * 8) * HW_ + r);
    float4 v0 = *p0, v1 = *p1, v2 = *p2, v3 = *p3;
    float bo = b_off[oc];
    float4 o;
    o.x = tanhf(v0.x + v1.x + v2.x + v3.x + bo);
    o.y = tanhf(v0.y + v1.y + v2.y + v3.y + bo);
    o.z = tanhf(v0.z + v1.z + v2.z + v3.z + bo);
    o.w = tanhf(v0.w + v1.w + v2.w + v3.w + bo);
    *(float4*)(d_off + e) = o;
}

// ---------------------------------------------------------------------------
// K3: offset upsample + grid_sample. Channel-PAIR packed smem tile
//     ([pair][pixel][2]) -> float2 gathers serve channels c and c+16 at once;
//     bilinear weights precomputed in Phase A. Block = 8x32 px, 512 thr.
// ---------------------------------------------------------------------------
#define K3P  127     // float2 pitch per pair row (126 used)
#define K3TW 18
#define K3TH 7
__global__ __launch_bounds__(512) void k3_sample(float* __restrict__ out) {
    int bx = blockIdx.x;
    int ys0 = (bx >> 2) * 8;
    int xs0 = (bx & 3) * 32;
    int g = blockIdx.y;
    int b = blockIdx.z;
    int tid = threadIdx.x;
    int warp = tid >> 5;      // 0..15 = channel pair
    int lane = tid & 31;

    __shared__ float tile[16 * K3P * 2];   // [pair][p][h], 16.3KB
    __shared__ int   s_r[8][32][4];        // p-indices of 4 corners
    __shared__ float s_w[8][32][4];        // bilinear weights w00,w01,w10,w11

    const float SY = 63.0f / 127.0f;
    const float SO = 63.0f / 128.0f;

    int x_lo = max(0, (int)floorf(xs0 * SY - 0.4923f));
    int y_lo = max(0, (int)floorf(ys0 * SY - 0.4923f));

    // cp.async tile load into channel-pair packed layout
    const float* pb = d_p + (size_t)(b * G_ + g) * HW_ * CG_;
    {
        uint32_t st0 = (uint32_t)__cvta_generic_to_shared(&tile[0]);
#pragma unroll
        for (int idx = tid; idx < K3TH * K3TW * CG_; idx += 512) {
            int p = idx >> 5;
            int c = idx & 31;
            int y = min(y_lo + p / K3TW, H_ - 1);
            int xx = min(x_lo + p % K3TW, W_ - 1);
            const float* src = &pb[(y * W_ + xx) * CG_ + c];
            uint32_t dst = st0 + (uint32_t)(((c & 15) * K3P + p) * 2 + (c >> 4)) * 4u;
            asm volatile("cp.async.ca.shared.global [%0], [%1], 4;"
                         :: "r"(dst), "l"(src));
        }
        asm volatile("cp.async.commit_group;");
    }

    // Phase A: 256 threads compute coords + packed bilinear weights
    if (tid < 256) {
        int r = tid >> 5;
        int xl = tid & 31;
        int ys = ys0 + r;
        int xs = xs0 + xl;

        float py = ys * SY;
        int y0u = (int)py;
        float wyu = py - y0u;
        int y1u = min(y0u + 1, H_ - 1);
        float px = xs * SY;
        int x0u = (int)px;
        float wxu = px - x0u;
        int x1u = min(x0u + 1, W_ - 1);

        const float* offx = d_off + (size_t)(b * 8 + 2 * g) * HW_;
        const float* offy = offx + HW_;

        float a00 = offx[y0u * W_ + x0u], a01 = offx[y0u * W_ + x1u];
        float a10 = offx[y1u * W_ + x0u], a11 = offx[y1u * W_ + x1u];
        float o_x = (a00 * (1.f - wxu) + a01 * wxu) * (1.f - wyu)
                  + (a10 * (1.f - wxu) + a11 * wxu) * wyu;

        float c00 = offy[y0u * W_ + x0u], c01 = offy[y0u * W_ + x1u];
        float c10 = offy[y1u * W_ + x0u], c11 = offy[y1u * W_ + x1u];
        float o_y = (c00 * (1.f - wxu) + c01 * wxu) * (1.f - wyu)
                  + (c10 * (1.f - wxu) + c11 * wxu) * wyu;

        float ix = fminf(fmaxf(px + o_x * SO, 0.f), (float)(W_ - 1));
        float iy = fminf(fmaxf(py + o_y * SO, 0.f), (float)(H_ - 1));

        int ix0 = (int)ix; if (ix0 > W_ - 1) ix0 = W_ - 1;
        int iy0 = (int)iy; if (iy0 > H_ - 1) iy0 = H_ - 1;
        int ix1 = min(ix0 + 1, W_ - 1);
        int iy1 = min(iy0 + 1, H_ - 1);
        float fx = ix - ix0;
        float fy = iy - iy0;

        int base = (iy0 - y_lo) * K3TW + (ix0 - x_lo);
        int dxo = ix1 - ix0;
        int dyo = (iy1 - iy0) * K3TW;
        s_r[r][xl][0] = base;
        s_r[r][xl][1] = base + dxo;
        s_r[r][xl][2] = base + dyo;
        s_r[r][xl][3] = base + dyo + dxo;
        s_w[r][xl][0] = (1.f - fx) * (1.f - fy);
        s_w[r][xl][1] = fx * (1.f - fy);
        s_w[r][xl][2] = (1.f - fx) * fy;
        s_w[r][xl][3] = fx * fy;
    }

    asm volatile("cp.async.wait_group 0;" ::: "memory");
    __syncthreads();

    // Phase B: warp = channel pair (c, c+16); lane = x pixel; float2 gathers
    const float2* tc = (const float2*)&tile[warp * K3P * 2];
    float* ob0 = out + ((size_t)(b * C_ + g * CG_ + warp) * HS_ + ys0) * WS_ + xs0 + lane;
    float* ob1 = ob0 + (size_t)16 * HS_ * WS_;
#pragma unroll
    for (int r = 0; r < 8; r++) {
        int4 rr = *(const int4*)&s_r[r][lane][0];
        float4 w = *(const float4*)&s_w[r][lane][0];
        float2 v00 = tc[rr.x];
        float2 v01 = tc[rr.y];
        float2 v10 = tc[rr.z];
        float2 v11 = tc[rr.w];
        float2 res = fma2(v00, make_float2(w.x, w.x),
                     fma2(v01, make_float2(w.y, w.y),
                     fma2(v10, make_float2(w.z, w.z),
                     mul2(v11, make_float2(w.w, w.w)))));
        ob0[(size_t)r * WS_] = res.x;
        ob1[(size_t)r * WS_] = res.y;
    }
}

// ---------------------------------------------------------------------------
// Launcher: fork-join two-stream schedule (graph-capturable).
//   null stream:  k2a -> k2b ----\
//   side stream:  k0  -> k1  -----+--> k3
// ---------------------------------------------------------------------------
extern "C" void kernel_launch(void* const* d_in, const int* in_sizes, int n_in,
                              void* d_out, int out_size) {
    const float* x      = (const float*)d_in[0];
    const float* w_off  = (const float*)d_in[1];
    const float* b_off  = (const float*)d_in[2];
    const float* w_proj = (const float*)d_in[3];
    const float* gamma  = (const float*)d_in[4];
    const float* beta   = (const float*)d_in[5];
    const float* mean   = (const float*)d_in[6];
    const float* var    = (const float*)d_in[7];
    float* out = (float*)d_out;

    static cudaStream_t s2 = nullptr;
    static cudaEvent_t evFork = nullptr, evJoin = nullptr;
    if (s2 == nullptr) {
        cudaStreamCreateWithFlags(&s2, cudaStreamNonBlocking);
        cudaEventCreateWithFlags(&evFork, cudaEventDisableTiming);
        cudaEventCreateWithFlags(&evJoin, cudaEventDisableTiming);
    }

    cudaEventRecord(evFork, 0);
    cudaStreamWaitEvent(s2, evFork, 0);

    // side stream: weight prep -> projection GEMM
    k0_prep<<<64, 256, 0, s2>>>(w_proj, gamma, beta, mean, var);
    dim3 g1(HW_ / 128, B_);
    k1_mma<<<g1, 256, 0, s2>>>(x);
    cudaEventRecord(evJoin, s2);

    // null stream: offset conv -> reduce
    dim3 g2(W_ / 32, H_ / 16, B_ * 4);
    k2a_conv3<<<g2, dim3(16, 16)>>>(x, w_off);
    int n4 = B_ * 8 * HW_ / 4;
    k2b_reduce<<<(n4 + 255) / 256, 256>>>(b_off);

    // join, then sample
    cudaStreamWaitEvent(0, evJoin, 0);
    dim3 g3((HS_ / 8) * (WS_ / 32), G_, B_);
    k3_sample<<<g3, 512>>>(out);
}

// round 14
// speedup vs baseline: 1.1101x; 1.0005x over previous
#include <cuda_runtime.h>
#include <math.h>
#include <stdint.h>

// Problem constants (fixed shapes)
#define B_  16
#define C_  128
#define H_  64
#define W_  64
#define G_  4
#define CG_ 32
#define HW_ 4096      // H_*W_
#define HS_ 128
#define WS_ 128

// Scratch (static device globals; no runtime allocation)
__device__ uint32_t d_Wt[C_ * C_];         // Wt[k][n] = tf32(w_proj[n,k] * bn_scale[n])
__device__ float d_tb[C_];                 // folded bias
__device__ float d_p[B_ * G_ * HW_ * CG_]; // p in (b,g,pix,cg) layout, 33.5MB
__device__ float d_off[B_ * 8 * HW_];      // tanh offsets, NCHW (B,2G,H,W)
__device__ float d_part[4 * B_ * 8 * HW_]; // K2 k-split partial sums, 8MB

// ---- packed fp32x2 helpers ----
__device__ __forceinline__ float2 fma2(float2 a, float2 b, float2 c) {
    float2 d;
    asm("fma.rn.f32x2 %0, %1, %2, %3;"
        : "=l"(reinterpret_cast<unsigned long long&>(d))
        : "l"(reinterpret_cast<unsigned long long&>(a)),
          "l"(reinterpret_cast<unsigned long long&>(b)),
          "l"(reinterpret_cast<unsigned long long&>(c)));
    return d;
}
__device__ __forceinline__ float2 mul2(float2 a, float2 b) {
    float2 d;
    asm("mul.rn.f32x2 %0, %1, %2;"
        : "=l"(reinterpret_cast<unsigned long long&>(d))
        : "l"(reinterpret_cast<unsigned long long&>(a)),
          "l"(reinterpret_cast<unsigned long long&>(b)));
    return d;
}
__device__ __forceinline__ uint32_t to_tf32(float v) {
    uint32_t u;
    asm("cvt.rna.tf32.f32 %0, %1;" : "=r"(u) : "f"(v));
    return u;
}

// ---------------------------------------------------------------------------
// K0: fold BN into transposed weights (tf32-rounded) + folded bias
// ---------------------------------------------------------------------------
__global__ void k0_prep(const float* __restrict__ w_proj,
                        const float* __restrict__ gamma,
                        const float* __restrict__ beta,
                        const float* __restrict__ mean,
                        const float* __restrict__ var) {
    int idx = blockIdx.x * blockDim.x + threadIdx.x;
    if (idx >= C_ * C_) return;
    int k = idx >> 7;
    int n = idx & 127;
    float s = gamma[n] * rsqrtf(var[n] + 1e-5f);
    d_Wt[k * C_ + n] = to_tf32(w_proj[n * C_ + k] * s);
    if (idx < C_) {
        d_tb[idx] = beta[idx] - mean[idx] * (gamma[idx] * rsqrtf(var[idx] + 1e-5f));
    }
}

// ---------------------------------------------------------------------------
// K1: 1x1 conv as TF32 mma.sync GEMM, double-buffered 16-k panels.
// ---------------------------------------------------------------------------
#define KP    16
#define SKSTR 136
__global__ __launch_bounds__(256) void k1_mma(const float* __restrict__ x) {
    __shared__ uint32_t As[2][KP * SKSTR];
    __shared__ uint32_t Bs[2][KP * SKSTR];
    __shared__ float sTb[128];

    int b = blockIdx.y;
    int pix0 = blockIdx.x * 128;
    int t = threadIdx.x;
    int wid = t >> 5;
    int lane = t & 31;
    int gid = lane >> 2;
    int tg = lane & 3;
    int mbase = (wid & 3) * 32;
    int nbase = (wid >> 2) * 64;

    if (t < 128) sTb[t] = d_tb[t];

    const float* xb = x + (size_t)b * C_ * HW_ + pix0;

    int fk[2], fc[2];
#pragma unroll
    for (int i = 0; i < 2; i++) {
        int s = t + i * 256;
        fk[i] = s >> 5;
        fc[i] = (s & 31) * 4;
    }

    float4 stg[2];

#define K1_STAGE_A(p) do { _Pragma("unroll") \
    for (int i = 0; i < 2; i++) \
        stg[i] = *(const float4*)&xb[(size_t)((p) * KP + fk[i]) * HW_ + fc[i]]; } while (0)

#define K1_COMMIT_A(p) do { uint32_t* Ad = As[(p) & 1]; _Pragma("unroll") \
    for (int i = 0; i < 2; i++) { uint32_t* d = Ad + fk[i] * SKSTR + fc[i]; \
        d[0] = to_tf32(stg[i].x); d[1] = to_tf32(stg[i].y); \
        d[2] = to_tf32(stg[i].z); d[3] = to_tf32(stg[i].w); } } while (0)

#define K1_FILL_B(p) do { \
    uint32_t sb = (uint32_t)__cvta_generic_to_shared(Bs[(p) & 1]); \
    _Pragma("unroll") for (int i = 0; i < 2; i++) { \
        uint32_t dst = sb + (uint32_t)(fk[i] * SKSTR + fc[i]) * 4u; \
        const uint32_t* src = d_Wt + ((p) * KP + fk[i]) * C_ + fc[i]; \
        asm volatile("cp.async.ca.shared.global [%0], [%1], 16;" :: "r"(dst), "l"(src)); } \
    asm volatile("cp.async.commit_group;"); } while (0)

    K1_STAGE_A(0);
    K1_FILL_B(0);
    K1_COMMIT_A(0);
    asm volatile("cp.async.wait_group 0;" ::: "memory");
    __syncthreads();

    float acc[2][8][4];
#pragma unroll
    for (int mt = 0; mt < 2; mt++)
#pragma unroll
        for (int nt = 0; nt < 8; nt++)
#pragma unroll
            for (int z = 0; z < 4; z++) acc[mt][nt][z] = 0.f;

#pragma unroll 1
    for (int p = 0; p < 8; p++) {
        if (p < 7) { K1_STAGE_A(p + 1); K1_FILL_B(p + 1); }

        const uint32_t* A = As[p & 1];
        const uint32_t* Bp = Bs[p & 1];

#pragma unroll
        for (int ks = 0; ks < 2; ks++) {
            int kk = ks * 8;
            uint32_t a[2][4];
#pragma unroll
            for (int mt = 0; mt < 2; mt++) {
                int m = mbase + mt * 16 + gid;
                const uint32_t* ap = A + (kk + tg) * SKSTR + m;
                a[mt][0] = ap[0];
                a[mt][1] = ap[8];
                a[mt][2] = ap[4 * SKSTR];
                a[mt][3] = ap[4 * SKSTR + 8];
            }
#pragma unroll
            for (int nt = 0; nt < 8; nt++) {
                int n = nbase + nt * 8 + gid;
                uint32_t b0 = Bp[(kk + tg) * SKSTR + n];
                uint32_t b1 = Bp[(kk + tg + 4) * SKSTR + n];
#pragma unroll
                for (int mt = 0; mt < 2; mt++) {
                    asm volatile(
                        "mma.sync.aligned.m16n8k8.row.col.f32.tf32.tf32.f32 "
                        "{%0,%1,%2,%3}, {%4,%5,%6,%7}, {%8,%9}, {%0,%1,%2,%3};"
                        : "+f"(acc[mt][nt][0]), "+f"(acc[mt][nt][1]),
                          "+f"(acc[mt][nt][2]), "+f"(acc[mt][nt][3])
                        : "r"(a[mt][0]), "r"(a[mt][1]), "r"(a[mt][2]), "r"(a[mt][3]),
                          "r"(b0), "r"(b1));
                }
            }
        }

        if (p < 7) {
            K1_COMMIT_A(p + 1);
            asm volatile("cp.async.wait_group 0;" ::: "memory");
        }
        __syncthreads();
    }

#pragma unroll
    for (int mt = 0; mt < 2; mt++) {
        int pixA = pix0 + mbase + mt * 16 + gid;
        int pixB = pixA + 8;
#pragma unroll
        for (int nt = 0; nt < 8; nt++) {
            int n = nbase + nt * 8 + 2 * tg;
            int g = n >> 5, cg = n & 31;
            float t0 = sTb[n], t1 = sTb[n + 1];
            float u;
            float2 vA, vB;
            u = acc[mt][nt][0] + t0; vA.x = u * (1.f / (1.f + __expf(-u)));
            u = acc[mt][nt][1] + t1; vA.y = u * (1.f / (1.f + __expf(-u)));
            u = acc[mt][nt][2] + t0; vB.x = u * (1.f / (1.f + __expf(-u)));
            u = acc[mt][nt][3] + t1; vB.y = u * (1.f / (1.f + __expf(-u)));
            float* base = d_p + ((size_t)(b * G_ + g) * HW_) * CG_ + cg;
            *(float2*)(base + (size_t)pixA * CG_) = vA;
            *(float2*)(base + (size_t)pixB * CG_) = vB;
        }
    }
}

// ---------------------------------------------------------------------------
// K2a: 3x3 conv partials, 32-channel k-slice, cp.async 4-deep pipeline.
// ---------------------------------------------------------------------------
#define XSTR 35
__global__ __launch_bounds__(256, 4) void k2a_conv3(const float* __restrict__ x,
                                                    const float* __restrict__ w_off) {
    __shared__ float ws[32 * 72];
    __shared__ float xbuf[4][18 * XSTR];

    int bz = blockIdx.z;
    int b = bz >> 2;
    int split = bz & 3;
    int k_lo = split * 32;
    int h0 = blockIdx.y * 16;
    int w0 = blockIdx.x * 32;
    int tid = threadIdx.y * 16 + threadIdx.x;
    int tx = threadIdx.x;
    int ty = threadIdx.y;

    for (int idx = tid; idx < 32 * 9 * 8; idx += 256) {
        int kk = idx / 72;
        int r = idx - kk * 72;
        int t = r >> 3;
        int oc = r & 7;
        ws[idx] = w_off[oc * (C_ * 9) + (k_lo + kk) * 9 + t];
    }
    for (int i = tid; i < 4 * 18 * XSTR; i += 256) ((float*)xbuf)[i] = 0.f;

    const float* xb = x + (size_t)b * C_ * HW_ + (size_t)k_lo * HW_;

    uint32_t soff[3];
    int goff[3];
    bool sval[3];
    uint32_t sb0 = (uint32_t)__cvta_generic_to_shared(&xbuf[0][0]);
#pragma unroll
    for (int i = 0; i < 3; i++) {
        int idx = tid + i * 256;
        int r = idx / 34, cc = idx - r * 34;
        int h = h0 - 1 + r, w = w0 - 1 + cc;
        soff[i] = (uint32_t)(r * XSTR + cc) * 4u;
        goff[i] = h * W_ + w;
        sval[i] = (idx < 612) && (h >= 0) && (h < H_) && (w >= 0) && (w < W_);
    }

    __syncthreads();

#pragma unroll
    for (int kk = 0; kk < 3; kk++) {
        const float* src = xb + (size_t)kk * HW_;
        uint32_t base = sb0 + (uint32_t)kk * (18 * XSTR * 4);
#pragma unroll
        for (int i = 0; i < 3; i++)
            if (sval[i])
                asm volatile("cp.async.ca.shared.global [%0], [%1], 4;"
                             :: "r"(base + soff[i]), "l"(src + goff[i]));
        asm volatile("cp.async.commit_group;");
    }

    float2 acc0[4], acc1[4];
#pragma unroll
    for (int q = 0; q < 4; q++) { acc0[q] = make_float2(0.f, 0.f); acc1[q] = make_float2(0.f, 0.f); }

    for (int k = 0; k < 32; k++) {
        asm volatile("cp.async.wait_group 2;" ::: "memory");
        __syncthreads();

        if (k + 3 < 32) {
            const float* src = xb + (size_t)(k + 3) * HW_;
            uint32_t base = sb0 + (uint32_t)((k + 3) & 3) * (18 * XSTR * 4);
#pragma unroll
            for (int i = 0; i < 3; i++)
                if (sval[i])
                    asm volatile("cp.async.ca.shared.global [%0], [%1], 4;"
                                 :: "r"(base + soff[i]), "l"(src + goff[i]));
        }
        asm volatile("cp.async.commit_group;");

        const float* xtc = &xbuf[k & 3][0];
        float xv[3][4];
#pragma unroll
        for (int r = 0; r < 3; r++)
#pragma unroll
            for (int c = 0; c < 4; c++) xv[r][c] = xtc[(ty + r) * XSTR + 2 * tx + c];

        const float* wk = &ws[k * 72];
#pragma unroll
        for (int t = 0; t < 9; t++) {
            int dy = t / 3, dx = t - dy * 3;
            float2 wp[4];
            *(float4*)&wp[0] = *(const float4*)&wk[t * 8 + 0];
            *(float4*)&wp[2] = *(const float4*)&wk[t * 8 + 4];
            float2 xp0 = make_float2(xv[dy][dx], xv[dy][dx]);
            float2 xp1 = make_float2(xv[dy][dx + 1], xv[dy][dx + 1]);
#pragma unroll
            for (int q = 0; q < 4; q++) {
                acc0[q] = fma2(xp0, wp[q], acc0[q]);
                acc1[q] = fma2(xp1, wp[q], acc1[q]);
            }
        }
    }

    int y = h0 + ty;
    int xw = w0 + 2 * tx;
    float* pbase = d_part + (size_t)(split * B_ + b) * 8 * HW_;
#pragma unroll
    for (int q = 0; q < 4; q++) {
        float a0[2] = { acc0[q].x, acc0[q].y };
        float a1[2] = { acc1[q].x, acc1[q].y };
#pragma unroll
        for (int h = 0; h < 2; h++) {
            int oc = q * 2 + h;
            size_t base = (size_t)oc * HW_ + y * W_ + xw;
            pbase[base] = a0[h];
            pbase[base + 1] = a1[h];
        }
    }
}

// ---------------------------------------------------------------------------
// K2b: reduce 4 partials + bias + tanh -> d_off
// ---------------------------------------------------------------------------
__global__ void k2b_reduce(const float* __restrict__ b_off) {
    int i = blockIdx.x * blockDim.x + threadIdx.x;
    const int N4 = B_ * 8 * HW_ / 4;
    if (i >= N4) return;
    int e = i * 4;
    int r = e & (8 * HW_ - 1);
    int b = e / (8 * HW_);
    int oc = r / HW_;

    const float4* p0 = (const float4*)(d_part + ((size_t)(0 * B_ + b) * 8) * HW_ + r);
    const float4* p1 = (const float4*)(d_part + ((size_t)(1 * B_ + b) * 8) * HW_ + r);
    const float4* p2 = (const float4*)(d_part + ((size_t)(2 * B_ + b) * 8) * HW_ + r);
    const float4* p3 = (const float4*)(d_part + ((size_t)(3 * B_ + b) * 8) * HW_ + r);
    float4 v0 = *p0, v1 = *p1, v2 = *p2, v3 = *p3;
    float bo = b_off[oc];
    float4 o;
    o.x = tanhf(v0.x + v1.x + v2.x + v3.x + bo);
    o.y = tanhf(v0.y + v1.y + v2.y + v3.y + bo);
    o.z = tanhf(v0.z + v1.z + v2.z + v3.z + bo);
    o.w = tanhf(v0.w + v1.w + v2.w + v3.w + bo);
    *(float4*)(d_off + e) = o;
}

// ---------------------------------------------------------------------------
// K3: offset upsample + grid_sample. Channel-pair packed smem tile;
//     16x32 output px per block (2048 blocks) to amortize fixed costs.
//     Bilinear weights precomputed in Phase A (all 512 threads).
// ---------------------------------------------------------------------------
#define K3TW 18
#define K3TH 10
#define K3P  181     // float2 pitch per pair row (180 used, odd)
__global__ __launch_bounds__(512) void k3_sample(float* __restrict__ out) {
    int bx = blockIdx.x;           // 0..31: 8 y-tiles x 4 x-tiles
    int ys0 = (bx >> 2) * 16;
    int xs0 = (bx & 3) * 32;
    int g = blockIdx.y;
    int b = blockIdx.z;
    int tid = threadIdx.x;
    int warp = tid >> 5;           // 0..15 = channel pair
    int lane = tid & 31;

    __shared__ float tile[16 * K3P * 2];    // [pair][p][h], 23.2KB
    __shared__ int   s_r[16][32][4];        // p-indices of 4 corners
    __shared__ float s_w[16][32][4];        // bilinear weights

    const float SY = 63.0f / 127.0f;
    const float SO = 63.0f / 128.0f;

    int x_lo = max(0, (int)floorf(xs0 * SY - 0.4923f));
    int y_lo = max(0, (int)floorf(ys0 * SY - 0.4923f));

    // cp.async tile load into channel-pair packed layout
    const float* pb = d_p + (size_t)(b * G_ + g) * HW_ * CG_;
    {
        uint32_t st0 = (uint32_t)__cvta_generic_to_shared(&tile[0]);
        for (int idx = tid; idx < K3TH * K3TW * CG_; idx += 512) {
            int p = idx >> 5;
            int c = idx & 31;
            int y = min(y_lo + p / K3TW, H_ - 1);
            int xx = min(x_lo + p % K3TW, W_ - 1);
            const float* src = &pb[(y * W_ + xx) * CG_ + c];
            uint32_t dst = st0 + (uint32_t)(((c & 15) * K3P + p) * 2 + (c >> 4)) * 4u;
            asm volatile("cp.async.ca.shared.global [%0], [%1], 4;"
                         :: "r"(dst), "l"(src));
        }
        asm volatile("cp.async.commit_group;");
    }

    // Phase A: all 512 threads compute one pixel's coords + bilinear weights
    {
        int r = tid >> 5;          // 0..15
        int xl = tid & 31;
        int ys = ys0 + r;
        int xs = xs0 + xl;

        float py = ys * SY;
        int y0u = (int)py;
        float wyu = py - y0u;
        int y1u = min(y0u + 1, H_ - 1);
        float px = xs * SY;
        int x0u = (int)px;
        float wxu = px - x0u;
        int x1u = min(x0u + 1, W_ - 1);

        const float* offx = d_off + (size_t)(b * 8 + 2 * g) * HW_;
        const float* offy = offx + HW_;

        float a00 = offx[y0u * W_ + x0u], a01 = offx[y0u * W_ + x1u];
        float a10 = offx[y1u * W_ + x0u], a11 = offx[y1u * W_ + x1u];
        float o_x = (a00 * (1.f - wxu) + a01 * wxu) * (1.f - wyu)
                  + (a10 * (1.f - wxu) + a11 * wxu) * wyu;

        float c00 = offy[y0u * W_ + x0u], c01 = offy[y0u * W_ + x1u];
        float c10 = offy[y1u * W_ + x0u], c11 = offy[y1u * W_ + x1u];
        float o_y = (c00 * (1.f - wxu) + c01 * wxu) * (1.f - wyu)
                  + (c10 * (1.f - wxu) + c11 * wxu) * wyu;

        float ix = fminf(fmaxf(px + o_x * SO, 0.f), (float)(W_ - 1));
        float iy = fminf(fmaxf(py + o_y * SO, 0.f), (float)(H_ - 1));

        int ix0 = (int)ix; if (ix0 > W_ - 1) ix0 = W_ - 1;
        int iy0 = (int)iy; if (iy0 > H_ - 1) iy0 = H_ - 1;
        int ix1 = min(ix0 + 1, W_ - 1);
        int iy1 = min(iy0 + 1, H_ - 1);
        float fx = ix - ix0;
        float fy = iy - iy0;

        int base = (iy0 - y_lo) * K3TW + (ix0 - x_lo);
        int dxo = ix1 - ix0;
        int dyo = (iy1 - iy0) * K3TW;
        s_r[r][xl][0] = base;
        s_r[r][xl][1] = base + dxo;
        s_r[r][xl][2] = base + dyo;
        s_r[r][xl][3] = base + dyo + dxo;
        s_w[r][xl][0] = (1.f - fx) * (1.f - fy);
        s_w[r][xl][1] = fx * (1.f - fy);
        s_w[r][xl][2] = (1.f - fx) * fy;
        s_w[r][xl][3] = fx * fy;
    }

    asm volatile("cp.async.wait_group 0;" ::: "memory");
    __syncthreads();

    // Phase B: warp = channel pair (c, c+16); lane = x pixel; 16 rows
    const float2* tc = (const float2*)&tile[warp * K3P * 2];
    float* ob0 = out + ((size_t)(b * C_ + g * CG_ + warp) * HS_ + ys0) * WS_ + xs0 + lane;
    float* ob1 = ob0 + (size_t)16 * HS_ * WS_;
#pragma unroll
    for (int r = 0; r < 16; r++) {
        int4 rr = *(const int4*)&s_r[r][lane][0];
        float4 w = *(const float4*)&s_w[r][lane][0];
        float2 v00 = tc[rr.x];
        float2 v01 = tc[rr.y];
        float2 v10 = tc[rr.z];
        float2 v11 = tc[rr.w];
        float2 res = fma2(v00, make_float2(w.x, w.x),
                     fma2(v01, make_float2(w.y, w.y),
                     fma2(v10, make_float2(w.z, w.z),
                     mul2(v11, make_float2(w.w, w.w)))));
        ob0[(size_t)r * WS_] = res.x;
        ob1[(size_t)r * WS_] = res.y;
    }
}

// ---------------------------------------------------------------------------
// Launcher: fork-join two-stream schedule (graph-capturable).
//   null stream:  k2a -> k2b ----\
//   side stream:  k0  -> k1  -----+--> k3
// ---------------------------------------------------------------------------
extern "C" void kernel_launch(void* const* d_in, const int* in_sizes, int n_in,
                              void* d_out, int out_size) {
    const float* x      = (const float*)d_in[0];
    const float* w_off  = (const float*)d_in[1];
    const float* b_off  = (const float*)d_in[2];
    const float* w_proj = (const float*)d_in[3];
    const float* gamma  = (const float*)d_in[4];
    const float* beta   = (const float*)d_in[5];
    const float* mean   = (const float*)d_in[6];
    const float* var    = (const float*)d_in[7];
    float* out = (float*)d_out;

    static cudaStream_t s2 = nullptr;
    static cudaEvent_t evFork = nullptr, evJoin = nullptr;
    if (s2 == nullptr) {
        cudaStreamCreateWithFlags(&s2, cudaStreamNonBlocking);
        cudaEventCreateWithFlags(&evFork, cudaEventDisableTiming);
        cudaEventCreateWithFlags(&evJoin, cudaEventDisableTiming);
    }

    cudaEventRecord(evFork, 0);
    cudaStreamWaitEvent(s2, evFork, 0);

    // side stream: weight prep -> projection GEMM
    k0_prep<<<64, 256, 0, s2>>>(w_proj, gamma, beta, mean, var);
    dim3 g1(HW_ / 128, B_);
    k1_mma<<<g1, 256, 0, s2>>>(x);
    cudaEventRecord(evJoin, s2);

    // null stream: offset conv -> reduce
    dim3 g2(W_ / 32, H_ / 16, B_ * 4);
    k2a_conv3<<<g2, dim3(16, 16)>>>(x, w_off);
    int n4 = B_ * 8 * HW_ / 4;
    k2b_reduce<<<(n4 + 255) / 256, 256>>>(b_off);

    // join, then sample
    cudaStreamWaitEvent(0, evJoin, 0);
    dim3 g3(32, G_, B_);
    k3_sample<<<g3, 512>>>(out);
}